// round 3
// baseline (speedup 1.0000x reference)
#include <cuda_runtime.h>

#define S      256
#define NB     128
#define L      256
#define NL     64
#define VOCAB  32000

#define RREG   192                 // T columns held in registers per thread
#define MG     ((S - RREG) / 4)    // 16 float4 groups of T in smem

// dynamic smem for scan kernel: Tsm4 (MG*256 float4) + xbuf[2][2][256] + tok[2][256]
#define SMEM1  (MG*256*16 + 2*2*256*4 + 2*256*4)

// scratch (device globals are the sanctioned way to get scratch)
__device__ float g_fwd[L * NB * S];   // fprime[t][b][s]  (pre-e-multiply forward)
__device__ float g_bwd[L * NB * S];   // b[t][b][s]

// ---------------------------------------------------------------------------
// K1: 128 CTAs x 256 threads. bid<64: forward chains for batches (2p,2p+1),
// bid>=64: backward chains. Thread i owns state i. T row (fwd) / T col (bwd):
// 192 columns in registers, 64 columns in smem (j-major, lane-contiguous).
// Recurrence: x_new[i] = (sum_j Trow_i[j] * x[j]) * e[t][i]
// Forward stores the pre-multiply value fprime; backward stores b itself.
// ---------------------------------------------------------------------------
__global__ __launch_bounds__(256, 1)
void hmm_scan_kernel(const void* __restrict__ sent_raw,
                     const float* __restrict__ emb,
                     const float* __restrict__ Tm)
{
    extern __shared__ char smem_raw[];
    float4* Tsm4 = (float4*)smem_raw;                          // MG*256 float4
    float*  xbuf = (float*)(smem_raw + MG*256*16);             // [2][2][256]
    int*    tok  = (int*)  (smem_raw + MG*256*16 + 4096);      // [2][256]
    __shared__ int s_i64;

    const int  i   = threadIdx.x;
    const int  bid = blockIdx.x;
    const bool bwd = (bid >= 64);
    const int  b0  = (bid & 63) * 2;
    const int  b1  = b0 + 1;

    // --- detect sentences dtype (int64 vs int32) ---
    if (i == 0) {
        const long long* s64 = (const long long*)sent_raw;
        int f = 1;
        for (int k = 0; k < 64; k++) {
            long long v = s64[k];
            if (v < 0 || v >= VOCAB) { f = 0; break; }
        }
        s_i64 = f;
    }
    __syncthreads();
    const int is64 = s_i64;

    // --- tokens for both chains into smem ---
    if (is64) {
        const long long* s64 = (const long long*)sent_raw;
        tok[i]       = (int)s64[b0 * L + i];
        tok[256 + i] = (int)s64[b1 * L + i];
    } else {
        const int* s32 = (const int*)sent_raw;
        tok[i]       = s32[b0 * L + i];
        tok[256 + i] = s32[b1 * L + i];
    }

    // --- T into registers (192 cols) + smem (64 cols) ---
    float4 Tr[RREG / 4];
    if (!bwd) {
        const float4* Trow = (const float4*)(Tm + i * S);
        #pragma unroll
        for (int g = 0; g < RREG / 4; g++) Tr[g] = Trow[g];
        #pragma unroll
        for (int g = 0; g < MG; g++) Tsm4[g * 256 + i] = Trow[RREG / 4 + g];
    } else {
        #pragma unroll
        for (int g = 0; g < RREG / 4; g++) {
            int j = g * 4;
            Tr[g] = make_float4(Tm[(j + 0) * S + i], Tm[(j + 1) * S + i],
                                Tm[(j + 2) * S + i], Tm[(j + 3) * S + i]);
        }
        #pragma unroll
        for (int g = 0; g < MG; g++) {
            int j = RREG + g * 4;
            Tsm4[g * 256 + i] = make_float4(Tm[(j + 0) * S + i], Tm[(j + 1) * S + i],
                                            Tm[(j + 2) * S + i], Tm[(j + 3) * S + i]);
        }
    }
    __syncthreads();

    float* outg = bwd ? g_bwd : g_fwd;

    // --- step 0 ---
    const int t0 = bwd ? (L - 1) : 0;
    float e0 = emb[tok[t0] * S + i];
    float e1 = emb[tok[256 + t0] * S + i];
    if (!bwd) {
        outg[(t0 * NB + b0) * S + i] = 1.0f;     // fprime[0] = 1
        outg[(t0 * NB + b1) * S + i] = 1.0f;
    } else {
        outg[(t0 * NB + b0) * S + i] = e0;       // b[L-1] = e[L-1]
        outg[(t0 * NB + b1) * S + i] = e1;
    }
    int p = 0;
    xbuf[p * 512 + i]       = e0;                // x = f[0] (or b[L-1]) = e
    xbuf[p * 512 + 256 + i] = e1;
    __syncthreads();

    const int tstep = bwd ? -1 : 1;
    int t = t0;

    for (int step = 1; step < L; step++) {
        t += tstep;
        // e for this step: issued early, consumed only after the mat-vec
        float en0 = emb[tok[t] * S + i];
        float en1 = emb[tok[256 + t] * S + i];

        const float4* x0 = (const float4*)(xbuf + p * 512);
        const float4* x1 = (const float4*)(xbuf + p * 512 + 256);

        float4 a0 = make_float4(0.f, 0.f, 0.f, 0.f);
        float4 a1 = make_float4(0.f, 0.f, 0.f, 0.f);

        #pragma unroll
        for (int g = 0; g < RREG / 4; g++) {
            float4 tv  = Tr[g];
            float4 xv0 = x0[g];
            float4 xv1 = x1[g];
            a0.x += tv.x * xv0.x; a0.y += tv.y * xv0.y;
            a0.z += tv.z * xv0.z; a0.w += tv.w * xv0.w;
            a1.x += tv.x * xv1.x; a1.y += tv.y * xv1.y;
            a1.z += tv.z * xv1.z; a1.w += tv.w * xv1.w;
        }
        #pragma unroll
        for (int g = 0; g < MG; g++) {
            float4 tv  = Tsm4[g * 256 + i];
            float4 xv0 = x0[RREG / 4 + g];
            float4 xv1 = x1[RREG / 4 + g];
            a0.x += tv.x * xv0.x; a0.y += tv.y * xv0.y;
            a0.z += tv.z * xv0.z; a0.w += tv.w * xv0.w;
            a1.x += tv.x * xv1.x; a1.y += tv.y * xv1.y;
            a1.z += tv.z * xv1.z; a1.w += tv.w * xv1.w;
        }
        float acc0 = (a0.x + a0.y) + (a0.z + a0.w);
        float acc1 = (a1.x + a1.y) + (a1.z + a1.w);

        float nx0 = acc0 * en0;
        float nx1 = acc1 * en1;

        if (!bwd) {
            outg[(t * NB + b0) * S + i] = acc0;  // fprime (pre-multiply)
            outg[(t * NB + b1) * S + i] = acc1;
        } else {
            outg[(t * NB + b0) * S + i] = nx0;   // b (with e)
            outg[(t * NB + b1) * S + i] = nx1;
        }

        p ^= 1;
        xbuf[p * 512 + i]       = nx0;
        xbuf[p * 512 + 256 + i] = nx1;
        __syncthreads();
    }
}

// ---------------------------------------------------------------------------
// K2: score[b][t][n] = sum_s fprime[t][b][s] * b[t][b][s] * O[s][n]
// Tiled SIMT GEMM: 512 blocks, tile = 64 rows (r = t*128+b) x 64 cols,
// 4x4 register blocking per thread, s-chunks of 64.
// ---------------------------------------------------------------------------
__global__ __launch_bounds__(256, 4)
void hmm_proj_kernel(const float* __restrict__ Om, float* __restrict__ outp)
{
    __shared__ float esm[64 * 68];   // stride 68: float4-aligned, bank-clean
    __shared__ float osm[64 * 64];

    const int tid = threadIdx.x;
    const int r0  = blockIdx.x * 64;
    const int rg  = tid >> 4;        // 16 row-groups of 4 rows
    const int cg  = tid & 15;        // 16 col-groups of 4 cols

    float4 acc0 = make_float4(0.f, 0.f, 0.f, 0.f);
    float4 acc1 = make_float4(0.f, 0.f, 0.f, 0.f);
    float4 acc2 = make_float4(0.f, 0.f, 0.f, 0.f);
    float4 acc3 = make_float4(0.f, 0.f, 0.f, 0.f);

    for (int s0 = 0; s0 < S; s0 += 64) {
        if (s0) __syncthreads();
        // load E = fprime * b for rows [r0, r0+64), s in [s0, s0+64)
        #pragma unroll
        for (int k = 0; k < 4; k++) {
            int id4 = k * 256 + tid;            // 0..1023 float4s
            int rr  = id4 >> 4;
            int ss  = (id4 & 15) * 4;
            int r   = r0 + rr;
            float4 fv = *(const float4*)&g_fwd[r * S + s0 + ss];
            float4 bv = *(const float4*)&g_bwd[r * S + s0 + ss];
            float4 ev = make_float4(fv.x * bv.x, fv.y * bv.y, fv.z * bv.z, fv.w * bv.w);
            *(float4*)&esm[rr * 68 + ss] = ev;
        }
        // load O chunk: rows [s0, s0+64), all 64 cols
        #pragma unroll
        for (int k = 0; k < 4; k++) {
            int id4 = k * 256 + tid;
            int ss  = id4 >> 4;
            int n   = (id4 & 15) * 4;
            *(float4*)&osm[ss * 64 + n] = *(const float4*)&Om[(s0 + ss) * NL + n];
        }
        __syncthreads();

        #pragma unroll 8
        for (int sc = 0; sc < 64; sc++) {
            float4 ov = *(const float4*)&osm[sc * 64 + cg * 4];
            float e0 = esm[(rg * 4 + 0) * 68 + sc];
            float e1 = esm[(rg * 4 + 1) * 68 + sc];
            float e2 = esm[(rg * 4 + 2) * 68 + sc];
            float e3 = esm[(rg * 4 + 3) * 68 + sc];
            acc0.x += e0 * ov.x; acc0.y += e0 * ov.y; acc0.z += e0 * ov.z; acc0.w += e0 * ov.w;
            acc1.x += e1 * ov.x; acc1.y += e1 * ov.y; acc1.z += e1 * ov.z; acc1.w += e1 * ov.w;
            acc2.x += e2 * ov.x; acc2.y += e2 * ov.y; acc2.z += e2 * ov.z; acc2.w += e2 * ov.w;
            acc3.x += e3 * ov.x; acc3.y += e3 * ov.y; acc3.z += e3 * ov.z; acc3.w += e3 * ov.w;
        }
    }

    // write: r = t*128 + b  ->  out[(b*L + t)*NL + n]
    #pragma unroll
    for (int k = 0; k < 4; k++) {
        int r  = r0 + rg * 4 + k;
        int t  = r >> 7;
        int bb = r & 127;
        float4 v = (k == 0) ? acc0 : (k == 1) ? acc1 : (k == 2) ? acc2 : acc3;
        *(float4*)&outp[(bb * L + t) * NL + cg * 4] = v;
    }
}

extern "C" void kernel_launch(void* const* d_in, const int* in_sizes, int n_in,
                              void* d_out, int out_size)
{
    (void)in_sizes; (void)n_in; (void)out_size;
    const void*  sent = d_in[0];
    const float* emb  = (const float*)d_in[1];
    const float* Tm   = (const float*)d_in[2];
    const float* Om   = (const float*)d_in[3];
    float* outp = (float*)d_out;

    cudaFuncSetAttribute(hmm_scan_kernel,
                         cudaFuncAttributeMaxDynamicSharedMemorySize, SMEM1);

    hmm_scan_kernel<<<128, 256, SMEM1>>>(sent, emb, Tm);
    hmm_proj_kernel<<<512, 256>>>(Om, outp);
}

// round 4
// speedup vs baseline: 1.2303x; 1.2303x over previous
#include <cuda_runtime.h>

#define S      256
#define NB     128
#define L      256
#define NL     64
#define VOCAB  32000

typedef unsigned long long ull;

// K1 T-split: per thread, per owned state: 96 T values in regs, 32 in smem
#define RPS    96
#define RG     (RPS/4)     // 24 float4 groups per state (regs)
#define SG     8           // 8 float4 groups per state (smem)

// K1 dynamic smem:
//   TsmU2 [2*SG][256] ulonglong2  = 65536 B
//   xs    [2][2][256] float       =  4096 B   (double-buffered state vec, per chain)
//   part  [2][2][256] float       =  4096 B   (partials: [chain][half][state])
//   tok   [2][256]    int         =  2048 B
#define SMEM1  (65536 + 4096 + 4096 + 2048)

// scratch
__device__ float g_fwd[L * NB * S];   // fprime[t][b][s]  (pre-e-multiply forward)
__device__ float g_bwd[L * NB * S];   // b[t][b][s]

__device__ __forceinline__ void ffma2(ull &a, ull b, ull c) {
    asm("fma.rn.f32x2 %0, %1, %2, %0;" : "+l"(a) : "l"(b), "l"(c));
}
__device__ __forceinline__ float hsum2(ull lo, ull hi) {
    float2 a = *reinterpret_cast<float2*>(&lo);
    float2 b = *reinterpret_cast<float2*>(&hi);
    return (a.x + a.y) + (b.x + b.y);
}

// ---------------------------------------------------------------------------
// K1: 128 CTAs x 256 threads, 2 chains per CTA. bid<64: forward for batches
// (2p, 2p+1); bid>=64: backward. Thread (h=tid>>7, u=tid&127) owns states
// {u, u+128} restricted to j in [128h, 128h+128). Dot products use packed
// fma.rn.f32x2 over j-pairs; halves combined through a smem partial buffer.
// ---------------------------------------------------------------------------
__global__ __launch_bounds__(256, 1)
void hmm_scan_kernel(const void* __restrict__ sent_raw,
                     const float* __restrict__ emb,
                     const float* __restrict__ Tm)
{
    extern __shared__ char smem_raw[];
    ulonglong2* TsmU2 = (ulonglong2*)smem_raw;              // [2*SG][256]
    float* xs   = (float*)(smem_raw + 65536);               // [p][c][j]
    float* part = (float*)(smem_raw + 65536 + 4096);        // [c][h][s]
    int*   tok  = (int*)  (smem_raw + 65536 + 8192);        // [c][t]
    __shared__ int s_i64;

    const int  tid = threadIdx.x;
    const int  h   = tid >> 7;
    const int  u   = tid & 127;
    const int  j0  = h << 7;
    const int  bid = blockIdx.x;
    const bool bwd = (bid >= 64);
    const int  b0  = (bid & 63) * 2;
    const int  b1  = b0 + 1;

    // --- detect sentences dtype (int64 vs int32) ---
    if (tid == 0) {
        const long long* s64 = (const long long*)sent_raw;
        int f = 1;
        for (int k = 0; k < 64; k++) {
            long long v = s64[k];
            if (v < 0 || v >= VOCAB) { f = 0; break; }
        }
        s_i64 = f;
    }
    __syncthreads();

    // --- tokens for both chains ---
    if (s_i64) {
        const long long* s64 = (const long long*)sent_raw;
        tok[tid]       = (int)s64[b0 * L + tid];
        tok[256 + tid] = (int)s64[b1 * L + tid];
    } else {
        const int* s32 = (const int*)sent_raw;
        tok[tid]       = s32[b0 * L + tid];
        tok[256 + tid] = s32[b1 * L + tid];
    }

    // --- T slices: state s0=u rows/cols j in [j0, j0+128) -> TrA; s1=u+128 -> TrB ---
    ull TrA[2 * RG], TrB[2 * RG];
    if (!bwd) {
        const float4* rowA = (const float4*)(Tm + u * S + j0);
        const float4* rowB = (const float4*)(Tm + (u + 128) * S + j0);
        #pragma unroll
        for (int g = 0; g < RG; g++) {
            ((float4*)TrA)[g] = rowA[g];
            ((float4*)TrB)[g] = rowB[g];
        }
        #pragma unroll
        for (int g = 0; g < SG; g++) {
            TsmU2[g * 256 + tid]        = ((const ulonglong2*)rowA)[RG + g];
            TsmU2[(SG + g) * 256 + tid] = ((const ulonglong2*)rowB)[RG + g];
        }
    } else {
        // T^T slices: element (s, j) = Tm[j*S + s]; lanes u consecutive -> coalesced
        #pragma unroll
        for (int g = 0; g < RG; g++) {
            int j = j0 + 4 * g;
            ((float4*)TrA)[g] = make_float4(Tm[(j+0)*S + u],       Tm[(j+1)*S + u],
                                            Tm[(j+2)*S + u],       Tm[(j+3)*S + u]);
            ((float4*)TrB)[g] = make_float4(Tm[(j+0)*S + u + 128], Tm[(j+1)*S + u + 128],
                                            Tm[(j+2)*S + u + 128], Tm[(j+3)*S + u + 128]);
        }
        #pragma unroll
        for (int g = 0; g < SG; g++) {
            int j = j0 + RPS + 4 * g;
            float4 a4 = make_float4(Tm[(j+0)*S + u],       Tm[(j+1)*S + u],
                                    Tm[(j+2)*S + u],       Tm[(j+3)*S + u]);
            float4 b4 = make_float4(Tm[(j+0)*S + u + 128], Tm[(j+1)*S + u + 128],
                                    Tm[(j+2)*S + u + 128], Tm[(j+3)*S + u + 128]);
            TsmU2[g * 256 + tid]        = *reinterpret_cast<ulonglong2*>(&a4);
            TsmU2[(SG + g) * 256 + tid] = *reinterpret_cast<ulonglong2*>(&b4);
        }
    }

    float* outg = bwd ? g_bwd : g_fwd;

    // --- step 0 ---
    const int t0 = bwd ? (L - 1) : 0;
    {
        float e0 = emb[tok[t0] * S + tid];
        float e1 = emb[tok[256 + t0] * S + tid];
        if (!bwd) {
            outg[(t0 * NB + b0) * S + tid] = 1.0f;    // fprime[0] = 1
            outg[(t0 * NB + b1) * S + tid] = 1.0f;
        } else {
            outg[(t0 * NB + b0) * S + tid] = e0;      // b[L-1] = e[L-1]
            outg[(t0 * NB + b1) * S + tid] = e1;
        }
        xs[tid]       = e0;                            // xs[p=0][c=0]
        xs[256 + tid] = e1;                            // xs[p=0][c=1]
    }
    __syncthreads();

    const int dt = bwd ? -1 : 1;
    int t = t0;
    int p = 0;

    for (int step = 1; step < L; step++) {
        t += dt;
        // e prefetch: issued now, consumed only in the combine phase
        float en0 = emb[tok[t] * S + tid];
        float en1 = emb[tok[256 + t] * S + tid];

        const ulonglong2* X0 = (const ulonglong2*)(xs + p * 512 + j0);
        const ulonglong2* X1 = (const ulonglong2*)(xs + p * 512 + 256 + j0);

        ull a00l = 0, a00h = 0, a01l = 0, a01h = 0;   // state u   : chain0, chain1
        ull a10l = 0, a10h = 0, a11l = 0, a11h = 0;   // state u+128

        #pragma unroll
        for (int g = 0; g < RG; g++) {
            ulonglong2 x0 = X0[g];
            ulonglong2 x1 = X1[g];
            ffma2(a00l, TrA[2*g],   x0.x); ffma2(a00h, TrA[2*g+1], x0.y);
            ffma2(a01l, TrA[2*g],   x1.x); ffma2(a01h, TrA[2*g+1], x1.y);
            ffma2(a10l, TrB[2*g],   x0.x); ffma2(a10h, TrB[2*g+1], x0.y);
            ffma2(a11l, TrB[2*g],   x1.x); ffma2(a11h, TrB[2*g+1], x1.y);
        }
        #pragma unroll
        for (int g = 0; g < SG; g++) {
            ulonglong2 tA = TsmU2[g * 256 + tid];
            ulonglong2 tB = TsmU2[(SG + g) * 256 + tid];
            ulonglong2 x0 = X0[RG + g];
            ulonglong2 x1 = X1[RG + g];
            ffma2(a00l, tA.x, x0.x); ffma2(a00h, tA.y, x0.y);
            ffma2(a01l, tA.x, x1.x); ffma2(a01h, tA.y, x1.y);
            ffma2(a10l, tB.x, x0.x); ffma2(a10h, tB.y, x0.y);
            ffma2(a11l, tB.x, x1.x); ffma2(a11h, tB.y, x1.y);
        }

        // partials: part[c][h][s]
        part[h * 256 + u]               = hsum2(a00l, a00h);
        part[h * 256 + u + 128]         = hsum2(a10l, a10h);
        part[512 + h * 256 + u]         = hsum2(a01l, a01h);
        part[512 + h * 256 + u + 128]   = hsum2(a11l, a11h);
        __syncthreads();

        // combine: thread tid handles state tid, both chains
        float s0 = part[tid]       + part[256 + tid];
        float s1 = part[512 + tid] + part[768 + tid];
        float nx0 = s0 * en0;
        float nx1 = s1 * en1;

        if (!bwd) {
            outg[(t * NB + b0) * S + tid] = s0;   // fprime
            outg[(t * NB + b1) * S + tid] = s1;
        } else {
            outg[(t * NB + b0) * S + tid] = nx0;  // b
            outg[(t * NB + b1) * S + tid] = nx1;
        }

        p ^= 1;
        xs[p * 512 + tid]       = nx0;
        xs[p * 512 + 256 + tid] = nx1;
        __syncthreads();
    }
}

// ---------------------------------------------------------------------------
// K2: score[b][t][n] = sum_s fprime[t][b][s] * b[t][b][s] * O[s][n]
// (unchanged from R2 — known good at 39 us; K2 is next round's target)
// ---------------------------------------------------------------------------
__global__ __launch_bounds__(256, 4)
void hmm_proj_kernel(const float* __restrict__ Om, float* __restrict__ outp)
{
    __shared__ float esm[64 * 68];
    __shared__ float osm[64 * 64];

    const int tid = threadIdx.x;
    const int r0  = blockIdx.x * 64;
    const int rg  = tid >> 4;
    const int cg  = tid & 15;

    float4 acc0 = make_float4(0.f, 0.f, 0.f, 0.f);
    float4 acc1 = make_float4(0.f, 0.f, 0.f, 0.f);
    float4 acc2 = make_float4(0.f, 0.f, 0.f, 0.f);
    float4 acc3 = make_float4(0.f, 0.f, 0.f, 0.f);

    for (int s0 = 0; s0 < S; s0 += 64) {
        if (s0) __syncthreads();
        #pragma unroll
        for (int k = 0; k < 4; k++) {
            int id4 = k * 256 + tid;
            int rr  = id4 >> 4;
            int ss  = (id4 & 15) * 4;
            int r   = r0 + rr;
            float4 fv = *(const float4*)&g_fwd[r * S + s0 + ss];
            float4 bv = *(const float4*)&g_bwd[r * S + s0 + ss];
            float4 ev = make_float4(fv.x * bv.x, fv.y * bv.y, fv.z * bv.z, fv.w * bv.w);
            *(float4*)&esm[rr * 68 + ss] = ev;
        }
        #pragma unroll
        for (int k = 0; k < 4; k++) {
            int id4 = k * 256 + tid;
            int ss  = id4 >> 4;
            int n   = (id4 & 15) * 4;
            *(float4*)&osm[ss * 64 + n] = *(const float4*)&Om[(s0 + ss) * NL + n];
        }
        __syncthreads();

        #pragma unroll 8
        for (int sc = 0; sc < 64; sc++) {
            float4 ov = *(const float4*)&osm[sc * 64 + cg * 4];
            float e0 = esm[(rg * 4 + 0) * 68 + sc];
            float e1 = esm[(rg * 4 + 1) * 68 + sc];
            float e2 = esm[(rg * 4 + 2) * 68 + sc];
            float e3 = esm[(rg * 4 + 3) * 68 + sc];
            acc0.x += e0 * ov.x; acc0.y += e0 * ov.y; acc0.z += e0 * ov.z; acc0.w += e0 * ov.w;
            acc1.x += e1 * ov.x; acc1.y += e1 * ov.y; acc1.z += e1 * ov.z; acc1.w += e1 * ov.w;
            acc2.x += e2 * ov.x; acc2.y += e2 * ov.y; acc2.z += e2 * ov.z; acc2.w += e2 * ov.w;
            acc3.x += e3 * ov.x; acc3.y += e3 * ov.y; acc3.z += e3 * ov.z; acc3.w += e3 * ov.w;
        }
    }

    #pragma unroll
    for (int k = 0; k < 4; k++) {
        int r  = r0 + rg * 4 + k;
        int t  = r >> 7;
        int bb = r & 127;
        float4 v = (k == 0) ? acc0 : (k == 1) ? acc1 : (k == 2) ? acc2 : acc3;
        *(float4*)&outp[(bb * L + t) * NL + cg * 4] = v;
    }
}

extern "C" void kernel_launch(void* const* d_in, const int* in_sizes, int n_in,
                              void* d_out, int out_size)
{
    (void)in_sizes; (void)n_in; (void)out_size;
    const void*  sent = d_in[0];
    const float* emb  = (const float*)d_in[1];
    const float* Tm   = (const float*)d_in[2];
    const float* Om   = (const float*)d_in[3];
    float* outp = (float*)d_out;

    cudaFuncSetAttribute(hmm_scan_kernel,
                         cudaFuncAttributeMaxDynamicSharedMemorySize, SMEM1);

    hmm_scan_kernel<<<128, 256, SMEM1>>>(sent, emb, Tm);
    hmm_proj_kernel<<<512, 256>>>(Om, outp);
}